// round 5
// baseline (speedup 1.0000x reference)
#include <cuda_runtime.h>

// SSIM loss, 16x3x512x512 f32, separable 11-tap Gaussian (sigma=1.5).
// All-scalar FFMA-imm version: literal taps (rt=1 imm-form on sm_103a),
// element-streamed H-conv from global, interleaved [mux,muy,Exx,Eyy] smem
// plane for LDS.128 V-conv, fused SSIM + deterministic reduction.

#define IMH 512
#define IMW 512
#define TILE_W 64
#define TILE_H 32
#define SROWS 42                 // TILE_H + 10 halo
#define NBLK (8 * 16 * 48)
#define C_OFF (SROWS * TILE_W * 4)       // 10752 floats (AB plane)
#define SMEM_FLOATS (C_OFF + SROWS * TILE_W)  // 13440
#define SMEM_BYTES (SMEM_FLOATS * 4)          // 53760

__device__ float g_partials[NBLK];
__device__ unsigned int g_count = 0;

// 1D Gaussian taps, sigma=1.5, ws=11, normalized. Compile-time constants so
// ptxas emits FFMA-imm (rt_SMSP=1, 2x the 3-reg FFMA rate).
static __device__ constexpr float Gw[11] = {
    0.00102838f, 0.00759876f, 0.03600078f, 0.10936070f, 0.21300553f,
    0.26601172f,
    0.21300553f, 0.10936070f, 0.03600078f, 0.00759876f, 0.00102838f};

// Accumulate one input column-element e (0..19) of the 20-col window into the
// 4 output columns it overlaps. Output cc uses window elems cc+3..cc+13 with
// tap t = e-3-cc (same accumulation order as before: t ascends with e).
__device__ __forceinline__ void acc_elem_ce(
    const int e, const float x, const float y,
    float* ax, float* ay, float* axx, float* ayy, float* axy) {
    if (e < 3 || e > 16) return;       // compile-time prune
    const float xx = x * x;
    const float yy = y * y;
    const float xy = x * y;
    #pragma unroll
    for (int cc = 0; cc < 4; cc++) {
        const int t = e - 3 - cc;
        if (t >= 0 && t < 11) {
            ax[cc]  = fmaf(x,  Gw[t], ax[cc]);
            ay[cc]  = fmaf(y,  Gw[t], ay[cc]);
            axx[cc] = fmaf(xx, Gw[t], axx[cc]);
            ayy[cc] = fmaf(yy, Gw[t], ayy[cc]);
            axy[cc] = fmaf(xy, Gw[t], axy[cc]);
        }
    }
}

extern "C" __global__ void __launch_bounds__(256, 4)
ssim_main(const float* __restrict__ gx, const float* __restrict__ gy,
          float* __restrict__ out) {
    extern __shared__ float sm[];
    __shared__ int s_last;

    const int tid = threadIdx.x;
    const int bx = blockIdx.x, by = blockIdx.y, p = blockIdx.z;
    const int c0 = bx * TILE_W;
    const int r0 = by * TILE_H;
    const float* px = gx + (size_t)p * IMH * IMW;
    const float* py = gy + (size_t)p * IMH * IMW;

    // ---------------- stage 1: horizontal conv, element-streamed -----------
    {
        const int tx = tid & 15;
        const int ty = tid >> 4;
        const int cb = tx * 4;               // output col base in tile
        const int gc0 = c0 + cb - 8;         // first window col (f4-aligned)
        const bool colsafe = (gc0 >= 0) && (gc0 + 19 < IMW);

        for (int i = ty; i < SROWS; i += 16) {
            const int gr = r0 - 5 + i;
            float ax[4]  = {0.f, 0.f, 0.f, 0.f};
            float ay[4]  = {0.f, 0.f, 0.f, 0.f};
            float axx[4] = {0.f, 0.f, 0.f, 0.f};
            float ayy[4] = {0.f, 0.f, 0.f, 0.f};
            float axy[4] = {0.f, 0.f, 0.f, 0.f};

            if (gr >= 0 && gr < IMH) {
                const float* rowx = px + (size_t)gr * IMW;
                const float* rowy = py + (size_t)gr * IMW;
                if (colsafe) {
                    #pragma unroll
                    for (int j = 0; j < 5; j++) {
                        const float4 vx = *(const float4*)(rowx + gc0 + 4 * j);
                        const float4 vy = *(const float4*)(rowy + gc0 + 4 * j);
                        acc_elem_ce(4 * j + 0, vx.x, vy.x, ax, ay, axx, ayy, axy);
                        acc_elem_ce(4 * j + 1, vx.y, vy.y, ax, ay, axx, ayy, axy);
                        acc_elem_ce(4 * j + 2, vx.z, vy.z, ax, ay, axx, ayy, axy);
                        acc_elem_ce(4 * j + 3, vx.w, vy.w, ax, ay, axx, ayy, axy);
                    }
                } else {
                    #pragma unroll
                    for (int j = 0; j < 5; j++) {
                        float fx[4], fy[4];
                        #pragma unroll
                        for (int r = 0; r < 4; r++) {
                            const int c = gc0 + 4 * j + r;
                            const bool ok = (c >= 0) && (c < IMW);
                            fx[r] = ok ? rowx[c] : 0.f;
                            fy[r] = ok ? rowy[c] : 0.f;
                        }
                        acc_elem_ce(4 * j + 0, fx[0], fy[0], ax, ay, axx, ayy, axy);
                        acc_elem_ce(4 * j + 1, fx[1], fy[1], ax, ay, axx, ayy, axy);
                        acc_elem_ce(4 * j + 2, fx[2], fy[2], ax, ay, axx, ayy, axy);
                        acc_elem_ce(4 * j + 3, fx[3], fy[3], ax, ay, axx, ayy, axy);
                    }
                }
            }

            // interleaved AB plane: per col [mu_x, mu_y, Exx, Eyy] (16B)
            float* ab = sm + (size_t)(i * TILE_W + cb) * 4;
            #pragma unroll
            for (int cc = 0; cc < 4; cc++)
                ((float4*)ab)[cc] =
                    make_float4(ax[cc], ay[cc], axx[cc], ayy[cc]);
            *(float4*)(sm + C_OFF + i * TILE_W + cb) =
                make_float4(axy[0], axy[1], axy[2], axy[3]);
        }
    }
    __syncthreads();

    // ---------------- stage 2: vertical conv (8-row strip) + SSIM ----------
    const int col = tid & 63;
    const int sgrp = tid >> 6;
    float amx[8], amy[8], aXX[8], aYY[8], aXY[8];
    #pragma unroll
    for (int i = 0; i < 8; i++) {
        amx[i] = 0.f; amy[i] = 0.f; aXX[i] = 0.f; aYY[i] = 0.f; aXY[i] = 0.f;
    }

    #pragma unroll
    for (int jr = 0; jr < 18; jr++) {
        const int hr = sgrp * 8 + jr;
        const float4 v = *(const float4*)(sm + (size_t)(hr * TILE_W + col) * 4);
        const float vc = sm[C_OFF + hr * TILE_W + col];
        #pragma unroll
        for (int i = 0; i < 8; i++) {
            const int t = jr - i;
            if (t >= 0 && t < 11) {
                amx[i] = fmaf(v.x, Gw[t], amx[i]);
                amy[i] = fmaf(v.y, Gw[t], amy[i]);
                aXX[i] = fmaf(v.z, Gw[t], aXX[i]);
                aYY[i] = fmaf(v.w, Gw[t], aYY[i]);
                aXY[i] = fmaf(vc,  Gw[t], aXY[i]);
            }
        }
    }

    float lsum = 0.f;
    #pragma unroll
    for (int i = 0; i < 8; i++) {
        const float mux = amx[i], muy = amy[i];
        const float mux2 = mux * mux;
        const float muy2 = muy * muy;
        const float muxy = mux * muy;
        const float sx2 = aXX[i] - mux2;
        const float sy2 = aYY[i] - muy2;
        const float sxy = aXY[i] - muxy;
        const float num = (2.f * muxy + 1e-4f) * (2.f * sxy + 9e-4f);
        const float den = (mux2 + muy2 + 1e-4f) * (sx2 + sy2 + 9e-4f) + 1e-12f;
        lsum += 1.f - __fdividef(num, den);
    }

    __syncthreads();   // all stage-2 smem reads done before smem reuse below
    #pragma unroll
    for (int o = 16; o > 0; o >>= 1)
        lsum += __shfl_down_sync(0xffffffffu, lsum, o);
    if ((tid & 31) == 0) sm[tid >> 5] = lsum;
    __syncthreads();
    if (tid == 0) {
        float s = 0.f;
        #pragma unroll
        for (int w = 0; w < 8; w++) s += sm[w];
        g_partials[(p * 16 + by) * 8 + bx] = s;
        __threadfence();
        const unsigned int old = atomicAdd(&g_count, 1u);
        s_last = (old == NBLK - 1) ? 1 : 0;
    }
    __syncthreads();

    // ---------------- last block: deterministic final reduction ------------
    if (s_last) {
        double s = 0.0;
        for (int i = tid; i < NBLK; i += 256) s += (double)g_partials[i];
        double* sd = (double*)sm;
        sd[tid] = s;
        __syncthreads();
        #pragma unroll
        for (int o = 128; o > 0; o >>= 1) {
            if (tid < o) sd[tid] += sd[tid + o];
            __syncthreads();
        }
        if (tid == 0) {
            out[0] = (float)(sd[0] * (1.0 / 12582912.0));
            g_count = 0;  // reset for next graph replay
        }
    }
}

extern "C" void kernel_launch(void* const* d_in, const int* in_sizes, int n_in,
                              void* d_out, int out_size) {
    const float* x = (const float*)d_in[0];
    const float* y = (const float*)d_in[1];
    float* out = (float*)d_out;

    cudaFuncSetAttribute(ssim_main, cudaFuncAttributeMaxDynamicSharedMemorySize,
                         SMEM_BYTES);
    dim3 grid(IMW / TILE_W, IMH / TILE_H, 48);
    ssim_main<<<grid, 256, SMEM_BYTES>>>(x, y, out);
}

// round 6
// speedup vs baseline: 1.0900x; 1.0900x over previous
#include <cuda_runtime.h>

// SSIM loss, 16x3x512x512 f32, separable 11-tap Gaussian (sigma=1.5).
// f32x2-packed H-conv loading raw (x,y) from global, smem H-planes,
// V-conv in regs, SSIM, fused deterministic reduction.
// 512-thread blocks, TILE 64x64 (SROWS=74): halo overhead 1.156x (was 1.31x).

#define IMH 512
#define IMW 512
#define TILE_W 64
#define TILE_H 64
#define SROWS 74                // TILE_H + 10 halo
#define HP 64
#define NBLK (8 * 8 * 48)       // 3072 blocks
#define OFF_A 0
#define OFF_B (SROWS * HP * 2)           // 9472 floats
#define OFF_C (2 * SROWS * HP * 2)       // 18944 floats
#define SMEM_FLOATS (OFF_C + SROWS * HP) // 23680
#define SMEM_BYTES (SMEM_FLOATS * 4)     // 94720

typedef unsigned long long ull;

__device__ float g_partials[NBLK];
__device__ unsigned int g_count = 0;

static __device__ constexpr float Gw[11] = {
    0.00102838f, 0.00759876f, 0.03600078f, 0.10936070f, 0.21300553f,
    0.26601172f,
    0.21300553f, 0.10936070f, 0.03600078f, 0.00759876f, 0.00102838f};

__device__ __forceinline__ ull pk2(float lo, float hi) {
    ull r;
    asm("mov.b64 %0, {%1,%2};" : "=l"(r) : "f"(lo), "f"(hi));
    return r;
}
__device__ __forceinline__ void upk(ull v, float& lo, float& hi) {
    asm("mov.b64 {%0,%1}, %2;" : "=f"(lo), "=f"(hi) : "l"(v));
}
__device__ __forceinline__ ull f2fma(ull a, ull b, ull c) {
    ull d;
    asm("fma.rn.f32x2 %0, %1, %2, %3;" : "=l"(d) : "l"(a), "l"(b), "l"(c));
    return d;
}
__device__ __forceinline__ ull f2mul(ull a, ull b) {
    ull d;
    asm("mul.rn.f32x2 %0, %1, %2;" : "=l"(d) : "l"(a), "l"(b));
    return d;
}

extern "C" __global__ void __launch_bounds__(512, 2)
ssim_main(const float* __restrict__ gx, const float* __restrict__ gy,
          float* __restrict__ out) {
    extern __shared__ float sm[];
    __shared__ int s_last;

    const int tid = threadIdx.x;
    const int bx = blockIdx.x, by = blockIdx.y, p = blockIdx.z;
    const int c0 = bx * TILE_W;
    const int r0 = by * TILE_H;
    const float* px = gx + (size_t)p * IMH * IMW;
    const float* py = gy + (size_t)p * IMH * IMW;

    ull GwP[11];
    #pragma unroll
    for (int t = 0; t < 11; t++) GwP[t] = pk2(Gw[t], Gw[t]);

    // ---------------- stage 1: horizontal conv (f32x2 packed) --------------
    {
        const int tx = tid & 15;
        const int ty = tid >> 4;             // 0..31, row stride 32
        const int cb = tx * 4;
        const int gc0 = c0 + cb - 8;
        const bool colsafe = (gc0 >= 0) && (gc0 + 19 < IMW);

        auto do_row = [&](const int i) {
            const int gr = r0 - 5 + i;
            float xq[20], yq[20];
            if (gr >= 0 && gr < IMH) {
                const float* rowx = px + (size_t)gr * IMW;
                const float* rowy = py + (size_t)gr * IMW;
                if (colsafe) {
                    #pragma unroll
                    for (int j = 0; j < 5; j++) {
                        const float4 v = *(const float4*)(rowx + gc0 + 4 * j);
                        xq[4 * j + 0] = v.x; xq[4 * j + 1] = v.y;
                        xq[4 * j + 2] = v.z; xq[4 * j + 3] = v.w;
                        const float4 w = *(const float4*)(rowy + gc0 + 4 * j);
                        yq[4 * j + 0] = w.x; yq[4 * j + 1] = w.y;
                        yq[4 * j + 2] = w.z; yq[4 * j + 3] = w.w;
                    }
                } else {
                    #pragma unroll
                    for (int e = 0; e < 20; e++) {
                        const int c = gc0 + e;
                        const bool ok = (c >= 0) && (c < IMW);
                        xq[e] = ok ? rowx[c] : 0.f;
                        yq[e] = ok ? rowy[c] : 0.f;
                    }
                }
            } else {
                #pragma unroll
                for (int e = 0; e < 20; e++) { xq[e] = 0.f; yq[e] = 0.f; }
            }

            ull vp[14];
            #pragma unroll
            for (int k = 0; k < 14; k++) vp[k] = pk2(xq[k + 3], yq[k + 3]);

            // (mu_x, mu_y)
            ull a0 = 0ull, a1 = 0ull, a2 = 0ull, a3 = 0ull;
            #pragma unroll
            for (int t = 0; t < 11; t++) {
                a0 = f2fma(vp[t + 0], GwP[t], a0);
                a1 = f2fma(vp[t + 1], GwP[t], a1);
                a2 = f2fma(vp[t + 2], GwP[t], a2);
                a3 = f2fma(vp[t + 3], GwP[t], a3);
            }
            {
                float* hA = sm + OFF_A + 2 * (i * HP + cb);
                ((ulonglong2*)hA)[0] = make_ulonglong2(a0, a1);
                ((ulonglong2*)hA)[1] = make_ulonglong2(a2, a3);
            }
            // xy stream directly from live scalars (no upk)
            float cr[14];
            #pragma unroll
            for (int k = 0; k < 14; k++) cr[k] = xq[k + 3] * yq[k + 3];
            // (x^2, y^2)
            #pragma unroll
            for (int k = 0; k < 14; k++) vp[k] = f2mul(vp[k], vp[k]);
            ull b0 = 0ull, b1 = 0ull, b2 = 0ull, b3 = 0ull;
            #pragma unroll
            for (int t = 0; t < 11; t++) {
                b0 = f2fma(vp[t + 0], GwP[t], b0);
                b1 = f2fma(vp[t + 1], GwP[t], b1);
                b2 = f2fma(vp[t + 2], GwP[t], b2);
                b3 = f2fma(vp[t + 3], GwP[t], b3);
            }
            {
                float* hB = sm + OFF_B + 2 * (i * HP + cb);
                ((ulonglong2*)hB)[0] = make_ulonglong2(b0, b1);
                ((ulonglong2*)hB)[1] = make_ulonglong2(b2, b3);
            }
            float c0a = 0.f, c1a = 0.f, c2a = 0.f, c3a = 0.f;
            #pragma unroll
            for (int t = 0; t < 11; t++) {
                c0a = fmaf(cr[t + 0], Gw[t], c0a);
                c1a = fmaf(cr[t + 1], Gw[t], c1a);
                c2a = fmaf(cr[t + 2], Gw[t], c2a);
                c3a = fmaf(cr[t + 3], Gw[t], c3a);
            }
            *(float4*)(sm + OFF_C + i * HP + cb) = make_float4(c0a, c1a, c2a, c3a);
        };

        do_row(ty);            // rows 0..31
        do_row(ty + 32);       // rows 32..63
        if (ty < SROWS - 64)   // rows 64..73 (ty < 10)
            do_row(ty + 64);
    }
    __syncthreads();

    // ---------------- stage 2: vertical conv (8-row strip) + SSIM ----------
    const int col = tid & 63;
    const int sgrp = tid >> 6;   // 0..7
    ull aA[8], aB[8];
    float aC[8];
    #pragma unroll
    for (int i = 0; i < 8; i++) { aA[i] = 0ull; aB[i] = 0ull; aC[i] = 0.f; }

    #pragma unroll
    for (int jr = 0; jr < 18; jr++) {
        const int hr = sgrp * 8 + jr;
        const ull vA = *(const ull*)(sm + OFF_A + 2 * (hr * HP + col));
        const ull vB = *(const ull*)(sm + OFF_B + 2 * (hr * HP + col));
        const float vC = sm[OFF_C + hr * HP + col];
        #pragma unroll
        for (int i = 0; i < 8; i++) {
            const int t = jr - i;
            if (t >= 0 && t < 11) {
                aA[i] = f2fma(vA, GwP[t], aA[i]);
                aB[i] = f2fma(vB, GwP[t], aB[i]);
                aC[i] = fmaf(vC, Gw[t], aC[i]);
            }
        }
    }

    float lsum = 0.f;
    #pragma unroll
    for (int i = 0; i < 8; i++) {
        float mux, muy, exx, eyy;
        upk(aA[i], mux, muy);
        upk(aB[i], exx, eyy);
        const float exy = aC[i];
        const float mux2 = mux * mux;
        const float muy2 = muy * muy;
        const float muxy = mux * muy;
        const float sx2 = exx - mux2;
        const float sy2 = eyy - muy2;
        const float sxy = exy - muxy;
        const float num = (2.f * muxy + 1e-4f) * (2.f * sxy + 9e-4f);
        const float den = (mux2 + muy2 + 1e-4f) * (sx2 + sy2 + 9e-4f) + 1e-12f;
        lsum += 1.f - __fdividef(num, den);
    }

    __syncthreads();   // stage-2 smem reads done before reuse
    #pragma unroll
    for (int o = 16; o > 0; o >>= 1)
        lsum += __shfl_down_sync(0xffffffffu, lsum, o);
    if ((tid & 31) == 0) sm[tid >> 5] = lsum;   // 16 warp sums
    __syncthreads();
    if (tid == 0) {
        float s = 0.f;
        #pragma unroll
        for (int w = 0; w < 16; w++) s += sm[w];
        g_partials[(p * 8 + by) * 8 + bx] = s;
        __threadfence();
        const unsigned int old = atomicAdd(&g_count, 1u);
        s_last = (old == NBLK - 1) ? 1 : 0;
    }
    __syncthreads();

    // ---------------- last block: deterministic final reduction ------------
    if (s_last) {
        double s = 0.0;
        for (int i = tid; i < NBLK; i += 512) s += (double)g_partials[i];
        double* sd = (double*)sm;
        sd[tid] = s;
        __syncthreads();
        #pragma unroll
        for (int o = 256; o > 0; o >>= 1) {
            if (tid < o) sd[tid] += sd[tid + o];
            __syncthreads();
        }
        if (tid == 0) {
            out[0] = (float)(sd[0] * (1.0 / 12582912.0));
            g_count = 0;  // reset for next graph replay
        }
    }
}

extern "C" void kernel_launch(void* const* d_in, const int* in_sizes, int n_in,
                              void* d_out, int out_size) {
    const float* x = (const float*)d_in[0];
    const float* y = (const float*)d_in[1];
    float* out = (float*)d_out;

    cudaFuncSetAttribute(ssim_main, cudaFuncAttributeMaxDynamicSharedMemorySize,
                         SMEM_BYTES);
    dim3 grid(IMW / TILE_W, IMH / TILE_H, 48);   // 8 x 8 x 48
    ssim_main<<<grid, 512, SMEM_BYTES>>>(x, y, out);
}

// round 7
// speedup vs baseline: 1.1342x; 1.0405x over previous
#include <cuda_runtime.h>

// SSIM loss, 16x3x512x512 f32, separable 11-tap Gaussian (sigma=1.5).
// f32x2-packed H-conv loading raw (x,y) from global, smem H-planes,
// V-conv in regs, SSIM, fused deterministic reduction.
// TILE 32x64 (tall): halo overhead 1.156x, 256-thread blocks, 4 blocks/SM.

#define IMH 512
#define IMW 512
#define TILE_W 32
#define TILE_H 64
#define SROWS 74                // TILE_H + 10 halo
#define HP 32                   // h-plane row width (cols)
#define NBLK (16 * 8 * 48)      // 6144 blocks
#define OFF_A 0
#define OFF_B (SROWS * HP * 2)           // 4736 floats
#define OFF_C (2 * SROWS * HP * 2)       // 9472 floats
#define SMEM_FLOATS (OFF_C + SROWS * HP) // 11840
#define SMEM_BYTES (SMEM_FLOATS * 4)     // 47360

typedef unsigned long long ull;

__device__ float g_partials[NBLK];
__device__ unsigned int g_count = 0;

static __device__ constexpr float Gw[11] = {
    0.00102838f, 0.00759876f, 0.03600078f, 0.10936070f, 0.21300553f,
    0.26601172f,
    0.21300553f, 0.10936070f, 0.03600078f, 0.00759876f, 0.00102838f};

__device__ __forceinline__ ull pk2(float lo, float hi) {
    ull r;
    asm("mov.b64 %0, {%1,%2};" : "=l"(r) : "f"(lo), "f"(hi));
    return r;
}
__device__ __forceinline__ void upk(ull v, float& lo, float& hi) {
    asm("mov.b64 {%0,%1}, %2;" : "=f"(lo), "=f"(hi) : "l"(v));
}
__device__ __forceinline__ ull f2fma(ull a, ull b, ull c) {
    ull d;
    asm("fma.rn.f32x2 %0, %1, %2, %3;" : "=l"(d) : "l"(a), "l"(b), "l"(c));
    return d;
}
__device__ __forceinline__ ull f2mul(ull a, ull b) {
    ull d;
    asm("mul.rn.f32x2 %0, %1, %2;" : "=l"(d) : "l"(a), "l"(b));
    return d;
}

extern "C" __global__ void __launch_bounds__(256, 4)
ssim_main(const float* __restrict__ gx, const float* __restrict__ gy,
          float* __restrict__ out) {
    extern __shared__ float sm[];
    __shared__ int s_last;

    const int tid = threadIdx.x;
    const int bx = blockIdx.x, by = blockIdx.y, p = blockIdx.z;
    const int c0 = bx * TILE_W;
    const int r0 = by * TILE_H;
    const float* px = gx + (size_t)p * IMH * IMW;
    const float* py = gy + (size_t)p * IMH * IMW;

    ull GwP[11];
    #pragma unroll
    for (int t = 0; t < 11; t++) GwP[t] = pk2(Gw[t], Gw[t]);

    // ---------------- stage 1: horizontal conv (f32x2 packed) --------------
    {
        const int tx = tid & 7;              // 8 groups of 4 output cols
        const int ty = tid >> 3;             // 0..31, row stride 32
        const int cb = tx * 4;
        const int gc0 = c0 + cb - 8;         // first window col (f4-aligned)
        const bool colsafe = (gc0 >= 0) && (gc0 + 19 < IMW);

        auto do_row = [&](const int i) {
            const int gr = r0 - 5 + i;
            float xq[20], yq[20];
            if (gr >= 0 && gr < IMH) {
                const float* rowx = px + (size_t)gr * IMW;
                const float* rowy = py + (size_t)gr * IMW;
                if (colsafe) {
                    #pragma unroll
                    for (int j = 0; j < 5; j++) {
                        const float4 v = *(const float4*)(rowx + gc0 + 4 * j);
                        xq[4 * j + 0] = v.x; xq[4 * j + 1] = v.y;
                        xq[4 * j + 2] = v.z; xq[4 * j + 3] = v.w;
                        const float4 w = *(const float4*)(rowy + gc0 + 4 * j);
                        yq[4 * j + 0] = w.x; yq[4 * j + 1] = w.y;
                        yq[4 * j + 2] = w.z; yq[4 * j + 3] = w.w;
                    }
                } else {
                    #pragma unroll
                    for (int e = 0; e < 20; e++) {
                        const int c = gc0 + e;
                        const bool ok = (c >= 0) && (c < IMW);
                        xq[e] = ok ? rowx[c] : 0.f;
                        yq[e] = ok ? rowy[c] : 0.f;
                    }
                }
            } else {
                #pragma unroll
                for (int e = 0; e < 20; e++) { xq[e] = 0.f; yq[e] = 0.f; }
            }

            ull vp[14];
            #pragma unroll
            for (int k = 0; k < 14; k++) vp[k] = pk2(xq[k + 3], yq[k + 3]);

            // (mu_x, mu_y)
            ull a0 = 0ull, a1 = 0ull, a2 = 0ull, a3 = 0ull;
            #pragma unroll
            for (int t = 0; t < 11; t++) {
                a0 = f2fma(vp[t + 0], GwP[t], a0);
                a1 = f2fma(vp[t + 1], GwP[t], a1);
                a2 = f2fma(vp[t + 2], GwP[t], a2);
                a3 = f2fma(vp[t + 3], GwP[t], a3);
            }
            {
                float* hA = sm + OFF_A + 2 * (i * HP + cb);
                ((ulonglong2*)hA)[0] = make_ulonglong2(a0, a1);
                ((ulonglong2*)hA)[1] = make_ulonglong2(a2, a3);
            }
            // xy stream directly from live scalars (no upk)
            float cr[14];
            #pragma unroll
            for (int k = 0; k < 14; k++) cr[k] = xq[k + 3] * yq[k + 3];
            // (x^2, y^2)
            #pragma unroll
            for (int k = 0; k < 14; k++) vp[k] = f2mul(vp[k], vp[k]);
            ull b0 = 0ull, b1 = 0ull, b2 = 0ull, b3 = 0ull;
            #pragma unroll
            for (int t = 0; t < 11; t++) {
                b0 = f2fma(vp[t + 0], GwP[t], b0);
                b1 = f2fma(vp[t + 1], GwP[t], b1);
                b2 = f2fma(vp[t + 2], GwP[t], b2);
                b3 = f2fma(vp[t + 3], GwP[t], b3);
            }
            {
                float* hB = sm + OFF_B + 2 * (i * HP + cb);
                ((ulonglong2*)hB)[0] = make_ulonglong2(b0, b1);
                ((ulonglong2*)hB)[1] = make_ulonglong2(b2, b3);
            }
            float c0a = 0.f, c1a = 0.f, c2a = 0.f, c3a = 0.f;
            #pragma unroll
            for (int t = 0; t < 11; t++) {
                c0a = fmaf(cr[t + 0], Gw[t], c0a);
                c1a = fmaf(cr[t + 1], Gw[t], c1a);
                c2a = fmaf(cr[t + 2], Gw[t], c2a);
                c3a = fmaf(cr[t + 3], Gw[t], c3a);
            }
            *(float4*)(sm + OFF_C + i * HP + cb) = make_float4(c0a, c1a, c2a, c3a);
        };

        do_row(ty);            // rows 0..31
        do_row(ty + 32);       // rows 32..63
        if (ty < SROWS - 64)   // rows 64..73
            do_row(ty + 64);
    }
    __syncthreads();

    // ---------------- stage 2: vertical conv (8-row strip) + SSIM ----------
    const int col = tid & 31;
    const int sgrp = tid >> 5;   // 0..7 strips of 8 output rows
    ull aA[8], aB[8];
    float aC[8];
    #pragma unroll
    for (int i = 0; i < 8; i++) { aA[i] = 0ull; aB[i] = 0ull; aC[i] = 0.f; }

    #pragma unroll
    for (int jr = 0; jr < 18; jr++) {
        const int hr = sgrp * 8 + jr;
        const ull vA = *(const ull*)(sm + OFF_A + 2 * (hr * HP + col));
        const ull vB = *(const ull*)(sm + OFF_B + 2 * (hr * HP + col));
        const float vC = sm[OFF_C + hr * HP + col];
        #pragma unroll
        for (int i = 0; i < 8; i++) {
            const int t = jr - i;
            if (t >= 0 && t < 11) {
                aA[i] = f2fma(vA, GwP[t], aA[i]);
                aB[i] = f2fma(vB, GwP[t], aB[i]);
                aC[i] = fmaf(vC, Gw[t], aC[i]);
            }
        }
    }

    float lsum = 0.f;
    #pragma unroll
    for (int i = 0; i < 8; i++) {
        float mux, muy, exx, eyy;
        upk(aA[i], mux, muy);
        upk(aB[i], exx, eyy);
        const float exy = aC[i];
        const float mux2 = mux * mux;
        const float muy2 = muy * muy;
        const float muxy = mux * muy;
        const float sx2 = exx - mux2;
        const float sy2 = eyy - muy2;
        const float sxy = exy - muxy;
        const float num = (2.f * muxy + 1e-4f) * (2.f * sxy + 9e-4f);
        const float den = (mux2 + muy2 + 1e-4f) * (sx2 + sy2 + 9e-4f) + 1e-12f;
        lsum += 1.f - __fdividef(num, den);
    }

    __syncthreads();   // stage-2 smem reads done before reuse
    #pragma unroll
    for (int o = 16; o > 0; o >>= 1)
        lsum += __shfl_down_sync(0xffffffffu, lsum, o);
    if ((tid & 31) == 0) sm[tid >> 5] = lsum;   // 8 warp sums
    __syncthreads();
    if (tid == 0) {
        float s = 0.f;
        #pragma unroll
        for (int w = 0; w < 8; w++) s += sm[w];
        g_partials[(p * 8 + by) * 16 + bx] = s;
        __threadfence();
        const unsigned int old = atomicAdd(&g_count, 1u);
        s_last = (old == NBLK - 1) ? 1 : 0;
    }
    __syncthreads();

    // ---------------- last block: deterministic final reduction ------------
    if (s_last) {
        double s = 0.0;
        for (int i = tid; i < NBLK; i += 256) s += (double)g_partials[i];
        double* sd = (double*)sm;
        sd[tid] = s;
        __syncthreads();
        #pragma unroll
        for (int o = 128; o > 0; o >>= 1) {
            if (tid < o) sd[tid] += sd[tid + o];
            __syncthreads();
        }
        if (tid == 0) {
            out[0] = (float)(sd[0] * (1.0 / 12582912.0));
            g_count = 0;  // reset for next graph replay
        }
    }
}

extern "C" void kernel_launch(void* const* d_in, const int* in_sizes, int n_in,
                              void* d_out, int out_size) {
    const float* x = (const float*)d_in[0];
    const float* y = (const float*)d_in[1];
    float* out = (float*)d_out;

    cudaFuncSetAttribute(ssim_main, cudaFuncAttributeMaxDynamicSharedMemorySize,
                         SMEM_BYTES);
    dim3 grid(IMW / TILE_W, IMH / TILE_H, 48);   // 16 x 8 x 48
    ssim_main<<<grid, 256, SMEM_BYTES>>>(x, y, out);
}

// round 9
// speedup vs baseline: 1.1534x; 1.0169x over previous
#include <cuda_runtime.h>

// SSIM loss, 16x3x512x512 f32, separable 11-tap Gaussian (sigma=1.5).
// TILE 32x64, 256-thread blocks, 4 blocks/SM. f32x2-packed H-conv from
// global; A/B H-planes interleaved (1 LDS.128 in V-pass); symmetric-tap
// dedup (6 packed tap regs); xy stream scattered with literal taps.

#define IMH 512
#define IMW 512
#define TILE_W 32
#define TILE_H 64
#define SROWS 74                // TILE_H + 10 halo
#define HP 32                   // h-plane row width (cols)
#define NBLK (16 * 8 * 48)      // 6144 blocks
#define OFF_C (SROWS * HP * 4)           // 9472 floats (AB interleaved plane)
#define SMEM_FLOATS (OFF_C + SROWS * HP) // 11840
#define SMEM_BYTES (SMEM_FLOATS * 4)     // 47360

typedef unsigned long long ull;

__device__ float g_partials[NBLK];
__device__ unsigned int g_count = 0;

static __device__ constexpr float Gw[11] = {
    0.00102838f, 0.00759876f, 0.03600078f, 0.10936070f, 0.21300553f,
    0.26601172f,
    0.21300553f, 0.10936070f, 0.03600078f, 0.00759876f, 0.00102838f};

__device__ __forceinline__ ull pk2(float lo, float hi) {
    ull r;
    asm("mov.b64 %0, {%1,%2};" : "=l"(r) : "f"(lo), "f"(hi));
    return r;
}
__device__ __forceinline__ void upk(ull v, float& lo, float& hi) {
    asm("mov.b64 {%0,%1}, %2;" : "=f"(lo), "=f"(hi) : "l"(v));
}
__device__ __forceinline__ ull f2fma(ull a, ull b, ull c) {
    ull d;
    asm("fma.rn.f32x2 %0, %1, %2, %3;" : "=l"(d) : "l"(a), "l"(b), "l"(c));
    return d;
}
__device__ __forceinline__ ull f2mul(ull a, ull b) {
    ull d;
    asm("mul.rn.f32x2 %0, %1, %2;" : "=l"(d) : "l"(a), "l"(b));
    return d;
}

// symmetric tap index: Gw[t] == Gw[10-t], keep 6 packed regs
#define TIX(t) ((t) < 6 ? (t) : 10 - (t))

extern "C" __global__ void __launch_bounds__(256, 4)
ssim_main(const float* __restrict__ gx, const float* __restrict__ gy,
          float* __restrict__ out) {
    extern __shared__ float sm[];
    __shared__ int s_last;

    const int tid = threadIdx.x;
    const int bx = blockIdx.x, by = blockIdx.y, p = blockIdx.z;
    const int c0 = bx * TILE_W;
    const int r0 = by * TILE_H;
    const float* px = gx + (size_t)p * IMH * IMW;
    const float* py = gy + (size_t)p * IMH * IMW;

    ull GwP[6];
    #pragma unroll
    for (int t = 0; t < 6; t++) GwP[t] = pk2(Gw[t], Gw[t]);

    // ---------------- stage 1: horizontal conv (f32x2 packed) --------------
    {
        const int tx = tid & 7;              // 8 groups of 4 output cols
        const int ty = tid >> 3;             // 0..31
        const int cb = tx * 4;
        const int gc0 = c0 + cb - 8;         // first window col (f4-aligned)
        const bool colsafe = (gc0 >= 0) && (gc0 + 19 < IMW);

        auto do_row = [&](const int i) {
            const int gr = r0 - 5 + i;
            float xq[20], yq[20];
            if (gr >= 0 && gr < IMH) {
                const float* rowx = px + (size_t)gr * IMW;
                const float* rowy = py + (size_t)gr * IMW;
                if (colsafe) {
                    #pragma unroll
                    for (int j = 0; j < 5; j++) {
                        const float4 v = *(const float4*)(rowx + gc0 + 4 * j);
                        xq[4 * j + 0] = v.x; xq[4 * j + 1] = v.y;
                        xq[4 * j + 2] = v.z; xq[4 * j + 3] = v.w;
                        const float4 w = *(const float4*)(rowy + gc0 + 4 * j);
                        yq[4 * j + 0] = w.x; yq[4 * j + 1] = w.y;
                        yq[4 * j + 2] = w.z; yq[4 * j + 3] = w.w;
                    }
                } else {
                    #pragma unroll
                    for (int e = 0; e < 20; e++) {
                        const int c = gc0 + e;
                        const bool ok = (c >= 0) && (c < IMW);
                        xq[e] = ok ? rowx[c] : 0.f;
                        yq[e] = ok ? rowy[c] : 0.f;
                    }
                }
            } else {
                #pragma unroll
                for (int e = 0; e < 20; e++) { xq[e] = 0.f; yq[e] = 0.f; }
            }

            // xy stream: per-element scatter with literal taps (FFMA-imm),
            // accumulation order (t ascending per output) preserved.
            float cac[4] = {0.f, 0.f, 0.f, 0.f};
            #pragma unroll
            for (int k = 0; k < 14; k++) {
                const float crv = xq[k + 3] * yq[k + 3];
                #pragma unroll
                for (int cc = 0; cc < 4; cc++) {
                    const int t = k - cc;
                    if (t >= 0 && t < 11)
                        cac[cc] = fmaf(crv, Gw[t], cac[cc]);
                }
            }

            ull vp[14];
            #pragma unroll
            for (int k = 0; k < 14; k++) vp[k] = pk2(xq[k + 3], yq[k + 3]);

            // (mu_x, mu_y)
            ull a0 = 0ull, a1 = 0ull, a2 = 0ull, a3 = 0ull;
            #pragma unroll
            for (int t = 0; t < 11; t++) {
                a0 = f2fma(vp[t + 0], GwP[TIX(t)], a0);
                a1 = f2fma(vp[t + 1], GwP[TIX(t)], a1);
                a2 = f2fma(vp[t + 2], GwP[TIX(t)], a2);
                a3 = f2fma(vp[t + 3], GwP[TIX(t)], a3);
            }
            // (x^2, y^2)
            #pragma unroll
            for (int k = 0; k < 14; k++) vp[k] = f2mul(vp[k], vp[k]);
            ull b0 = 0ull, b1 = 0ull, b2 = 0ull, b3 = 0ull;
            #pragma unroll
            for (int t = 0; t < 11; t++) {
                b0 = f2fma(vp[t + 0], GwP[TIX(t)], b0);
                b1 = f2fma(vp[t + 1], GwP[TIX(t)], b1);
                b2 = f2fma(vp[t + 2], GwP[TIX(t)], b2);
                b3 = f2fma(vp[t + 3], GwP[TIX(t)], b3);
            }
            // interleaved AB plane: 16B per column = {(mux,muy),(Exx,Eyy)}
            {
                float* ab = sm + (size_t)(i * HP + cb) * 4;
                ((ulonglong2*)ab)[0] = make_ulonglong2(a0, b0);
                ((ulonglong2*)ab)[1] = make_ulonglong2(a1, b1);
                ((ulonglong2*)ab)[2] = make_ulonglong2(a2, b2);
                ((ulonglong2*)ab)[3] = make_ulonglong2(a3, b3);
            }
            *(float4*)(sm + OFF_C + i * HP + cb) =
                make_float4(cac[0], cac[1], cac[2], cac[3]);
        };

        do_row(ty);            // rows 0..31
        do_row(ty + 32);       // rows 32..63
        if (ty < SROWS - 64)   // rows 64..73
            do_row(ty + 64);
    }
    __syncthreads();

    // ---------------- stage 2: vertical conv (8-row strip) + SSIM ----------
    const int col = tid & 31;
    const int sgrp = tid >> 5;   // 0..7 strips of 8 output rows
    ull aA[8], aB[8];
    float aC[8];
    #pragma unroll
    for (int i = 0; i < 8; i++) { aA[i] = 0ull; aB[i] = 0ull; aC[i] = 0.f; }

    #pragma unroll
    for (int jr = 0; jr < 18; jr++) {
        const int hr = sgrp * 8 + jr;
        const ulonglong2 vab =
            *(const ulonglong2*)(sm + (size_t)(hr * HP + col) * 4);
        const float vC = sm[OFF_C + hr * HP + col];
        #pragma unroll
        for (int i = 0; i < 8; i++) {
            const int t = jr - i;
            if (t >= 0 && t < 11) {
                aA[i] = f2fma(vab.x, GwP[TIX(t)], aA[i]);
                aB[i] = f2fma(vab.y, GwP[TIX(t)], aB[i]);
                aC[i] = fmaf(vC, Gw[t], aC[i]);
            }
        }
    }

    float lsum = 0.f;
    #pragma unroll
    for (int i = 0; i < 8; i++) {
        float mux, muy, exx, eyy;
        upk(aA[i], mux, muy);
        upk(aB[i], exx, eyy);
        const float exy = aC[i];
        const float mux2 = mux * mux;
        const float muy2 = muy * muy;
        const float muxy = mux * muy;
        const float sx2 = exx - mux2;
        const float sy2 = eyy - muy2;
        const float sxy = exy - muxy;
        const float num = (2.f * muxy + 1e-4f) * (2.f * sxy + 9e-4f);
        const float den = (mux2 + muy2 + 1e-4f) * (sx2 + sy2 + 9e-4f) + 1e-12f;
        lsum += 1.f - __fdividef(num, den);
    }

    __syncthreads();   // stage-2 smem reads done before reuse
    #pragma unroll
    for (int o = 16; o > 0; o >>= 1)
        lsum += __shfl_down_sync(0xffffffffu, lsum, o);
    if ((tid & 31) == 0) sm[tid >> 5] = lsum;   // 8 warp sums
    __syncthreads();
    if (tid == 0) {
        float s = 0.f;
        #pragma unroll
        for (int w = 0; w < 8; w++) s += sm[w];
        g_partials[(p * 8 + by) * 16 + bx] = s;
        __threadfence();
        const unsigned int old = atomicAdd(&g_count, 1u);
        s_last = (old == NBLK - 1) ? 1 : 0;
    }
    __syncthreads();

    // ---------------- last block: deterministic final reduction ------------
    if (s_last) {
        double s = 0.0;
        for (int i = tid; i < NBLK; i += 256) s += (double)g_partials[i];
        double* sd = (double*)sm;
        sd[tid] = s;
        __syncthreads();
        #pragma unroll
        for (int o = 128; o > 0; o >>= 1) {
            if (tid < o) sd[tid] += sd[tid + o];
            __syncthreads();
        }
        if (tid == 0) {
            out[0] = (float)(sd[0] * (1.0 / 12582912.0));
            g_count = 0;  // reset for next graph replay
        }
    }
}

extern "C" void kernel_launch(void* const* d_in, const int* in_sizes, int n_in,
                              void* d_out, int out_size) {
    const float* x = (const float*)d_in[0];
    const float* y = (const float*)d_in[1];
    float* out = (float*)d_out;

    cudaFuncSetAttribute(ssim_main, cudaFuncAttributeMaxDynamicSharedMemorySize,
                         SMEM_BYTES);
    dim3 grid(IMW / TILE_W, IMH / TILE_H, 48);   // 16 x 8 x 48
    ssim_main<<<grid, 256, SMEM_BYTES>>>(x, y, out);
}